// round 1
// baseline (speedup 1.0000x reference)
#include <cuda_runtime.h>
#include <math.h>

// Problem shape (fixed): x[16, 1024, 1024, 2] float32 NHWC
#define N_  16
#define H_  1024
#define W_  1024
#define C_  2
#define FS  61
#define RAD 30           // (FS-1)/2
#define DENOM 7442.0f    // FS*FS*C
#define EPS_ 1e-7f

#define TOT_F   (N_*H_*W_*C_)        // 33554432 floats
#define ROWS    (N_*H_)              // 16384
#define NCOL2   (N_*W_*C_)           // 32768 scalar columns (float view)
#define NCOL4   (N_*W_)              // 16384 float4 columns
#define SEG     4
#define ROWS_PER_SEG (H_/SEG)        // 256

// Scratch (static __device__ — no allocations allowed)
__device__ float  g_Vx[TOT_F];            // 128 MB: vertical box sums of x
__device__ float  g_out[TOT_F];           // 128 MB: out = x - avg(x)
__device__ float4 g_HB[N_*H_*W_];         // 256 MB: horiz window sums of (out, out^2), per channel

static __device__ __forceinline__ float2 f2add(float2 a, float2 b){ return make_float2(a.x+b.x, a.y+b.y); }
static __device__ __forceinline__ float2 f2sub(float2 a, float2 b){ return make_float2(a.x-b.x, a.y-b.y); }
static __device__ __forceinline__ float4 f4add(float4 a, float4 b){ return make_float4(a.x+b.x, a.y+b.y, a.z+b.z, a.w+b.w); }
static __device__ __forceinline__ float4 f4sub(float4 a, float4 b){ return make_float4(a.x-b.x, a.y-b.y, a.z-b.z, a.w-b.w); }

// ---------------------------------------------------------------------------
// K1: vertical sliding-window sum of x -> g_Vx.
// One thread per (n, w, c) column segment. Consecutive threads = consecutive
// (w,c) -> fully coalesced 128B lines. Lagged subtract re-reads (L2 hit).
// ---------------------------------------------------------------------------
__global__ __launch_bounds__(256) void k1_vbox(const float* __restrict__ x)
{
    int gid = blockIdx.x * blockDim.x + threadIdx.x;   // 131072 total
    int col = gid & (NCOL2 - 1);                       // 0..32767
    int seg = gid >> 15;                               // 0..3
    int n   = col >> 11;                               // col / 2048
    int rem = col & 2047;                              // w*2 + c
    size_t base = (size_t)n * (H_*W_*C_) + rem;
    const float* xp = x + base;
    float* vp = g_Vx + base;

    int r0 = seg * ROWS_PER_SEG;
    float sum = 0.f;
    // warm up: rows [r0-30, r0+29]
    for (int j = r0 - RAD; j < r0 + RAD; ++j)
        if (j >= 0) sum += xp[(size_t)j * (W_*C_)];

    #pragma unroll 4
    for (int h = r0; h < r0 + ROWS_PER_SEG; ++h) {
        int hn = h + RAD;
        if (hn < H_) sum += xp[(size_t)hn * (W_*C_)];
        vp[(size_t)h * (W_*C_)] = sum;
        int ho = h - RAD;
        if (ho >= 0) sum -= xp[(size_t)ho * (W_*C_)];
    }
}

// ---------------------------------------------------------------------------
// K2: one block per row (n*H+h). 256 threads x 4 items = 1024 w positions.
//  1) prefix-scan Vx row (float2, per-channel) -> horizontal window -> a
//  2) out = x - a  (store to g_out)
//  3) prefix-scan (out, out^2) as float4 -> horizontal window sums -> g_HB
// ---------------------------------------------------------------------------
__global__ __launch_bounds__(256) void k2_row(const float* __restrict__ x)
{
    const int row  = blockIdx.x;                 // n*H + h
    const int t    = threadIdx.x;
    const int lane = t & 31;
    const int wid  = t >> 5;
    const unsigned FULL = 0xffffffffu;

    const float2* xg = reinterpret_cast<const float2*>(x)     + (size_t)row * W_;
    const float2* vg = reinterpret_cast<const float2*>(g_Vx)  + (size_t)row * W_;
    float2*       og = reinterpret_cast<float2*>(g_out)       + (size_t)row * W_;
    float4*       hb = g_HB                                   + (size_t)row * W_;

    __shared__ float2 sP[W_];        // prefix of Vx row
    __shared__ float4 sQ[W_];        // prefix of (out, out^2)
    __shared__ float2 wsum2[8];
    __shared__ float4 wsum4[8];

    const int base = t * 4;

    // ---- load Vx + x chunks ----
    float2 v[4], xr[4];
    #pragma unroll
    for (int i = 0; i < 4; ++i) { v[i] = vg[base + i]; xr[i] = xg[base + i]; }

    // ---- scan #1: float2 inclusive prefix of Vx row ----
    #pragma unroll
    for (int i = 1; i < 4; ++i) v[i] = f2add(v[i], v[i-1]);
    float2 tot2 = v[3];
    float2 ws2 = tot2;
    #pragma unroll
    for (int d = 1; d < 32; d <<= 1) {
        float ux = __shfl_up_sync(FULL, ws2.x, d);
        float uy = __shfl_up_sync(FULL, ws2.y, d);
        if (lane >= d) { ws2.x += ux; ws2.y += uy; }
    }
    if (lane == 31) wsum2[wid] = ws2;
    __syncthreads();
    float2 off2 = f2sub(ws2, tot2);              // exclusive within warp
    for (int k = 0; k < wid; ++k) off2 = f2add(off2, wsum2[k]);
    #pragma unroll
    for (int i = 0; i < 4; ++i) sP[base + i] = f2add(off2, v[i]);
    __syncthreads();

    // ---- a = horiz window of sP / DENOM ; out = x - a ----
    const float inv = 1.0f / DENOM;
    float4 q[4];
    float2 o[4];
    #pragma unroll
    for (int i = 0; i < 4; ++i) {
        int w  = base + i;
        int hi = min(w + RAD, W_ - 1);
        float2 s = sP[hi];
        if (w >= RAD + 1) s = f2sub(s, sP[w - RAD - 1]);
        float2 a = make_float2(s.x * inv, s.y * inv);
        o[i] = f2sub(xr[i], a);
        og[w] = o[i];
        q[i] = make_float4(o[i].x, o[i].y, o[i].x * o[i].x, o[i].y * o[i].y);
    }

    // ---- scan #2: float4 inclusive prefix of (out, out^2) ----
    #pragma unroll
    for (int i = 1; i < 4; ++i) q[i] = f4add(q[i], q[i-1]);
    float4 tot4 = q[3];
    float4 ws4 = tot4;
    #pragma unroll
    for (int d = 1; d < 32; d <<= 1) {
        float ux = __shfl_up_sync(FULL, ws4.x, d);
        float uy = __shfl_up_sync(FULL, ws4.y, d);
        float uz = __shfl_up_sync(FULL, ws4.z, d);
        float uw = __shfl_up_sync(FULL, ws4.w, d);
        if (lane >= d) { ws4.x += ux; ws4.y += uy; ws4.z += uz; ws4.w += uw; }
    }
    if (lane == 31) wsum4[wid] = ws4;
    __syncthreads();
    float4 off4 = f4sub(ws4, tot4);
    for (int k = 0; k < wid; ++k) off4 = f4add(off4, wsum4[k]);
    #pragma unroll
    for (int i = 0; i < 4; ++i) sQ[base + i] = f4add(off4, q[i]);
    __syncthreads();

    // ---- horizontal window sums of (out, out^2) -> g_HB ----
    #pragma unroll
    for (int i = 0; i < 4; ++i) {
        int w  = base + i;
        int hi = min(w + RAD, W_ - 1);
        float4 s = sQ[hi];
        if (w >= RAD + 1) s = f4sub(s, sQ[w - RAD - 1]);
        hb[w] = s;
    }
}

// ---------------------------------------------------------------------------
// K3: vertical sliding float4 sum of g_HB -> (b, c); finalize:
//     res = out / (sqrt(c - b^2) + eps)
// Thread per (n, w) column segment; float4 + float2 accesses coalesced.
// ---------------------------------------------------------------------------
__global__ __launch_bounds__(256) void k3_vfin(float* __restrict__ outp)
{
    int gid = blockIdx.x * blockDim.x + threadIdx.x;   // 65536 total
    int col = gid & (NCOL4 - 1);                       // 0..16383  (n, w)
    int seg = gid >> 14;                               // 0..3
    int n   = col >> 10;
    int w   = col & (W_ - 1);

    size_t cbase = (size_t)n * (H_*W_) + w;            // row stride = W_ (in float4 / float2 units)
    const float4* hb = g_HB + cbase;
    const float2* og = reinterpret_cast<const float2*>(g_out) + cbase;
    float2*       rp = reinterpret_cast<float2*>(outp) + cbase;

    int r0 = seg * ROWS_PER_SEG;
    float4 s = make_float4(0.f, 0.f, 0.f, 0.f);
    for (int j = r0 - RAD; j < r0 + RAD; ++j)
        if (j >= 0) s = f4add(s, hb[(size_t)j * W_]);

    const float inv = 1.0f / DENOM;
    #pragma unroll 4
    for (int h = r0; h < r0 + ROWS_PER_SEG; ++h) {
        int hn = h + RAD;
        if (hn < H_) s = f4add(s, hb[(size_t)hn * W_]);

        float b0 = s.x * inv, b1 = s.y * inv;
        float c0 = s.z * inv, c1 = s.w * inv;
        float sd0 = sqrtf(fmaxf(c0 - b0 * b0, 0.f)) + EPS_;
        float sd1 = sqrtf(fmaxf(c1 - b1 * b1, 0.f)) + EPS_;

        float2 o = og[(size_t)h * W_];
        float2 r;
        r.x = o.x / sd0;
        r.y = o.y / sd1;
        rp[(size_t)h * W_] = r;

        int ho = h - RAD;
        if (ho >= 0) s = f4sub(s, hb[(size_t)ho * W_]);
    }
}

extern "C" void kernel_launch(void* const* d_in, const int* in_sizes, int n_in,
                              void* d_out, int out_size)
{
    const float* x = (const float*)d_in[0];
    (void)in_sizes; (void)n_in; (void)out_size;

    k1_vbox<<<(NCOL2 * SEG) / 256, 256>>>(x);          // 512 blocks
    k2_row <<<ROWS, 256>>>(x);                          // 16384 blocks
    k3_vfin<<<(NCOL4 * SEG) / 256, 256>>>((float*)d_out); // 256 blocks
}

// round 16
// speedup vs baseline: 1.4183x; 1.4183x over previous
#include <cuda_runtime.h>
#include <math.h>

// Problem shape (fixed): x[16, 1024, 1024, 2] float32 NHWC
#define N_  16
#define H_  1024
#define W_  1024
#define C_  2
#define FS  61
#define RAD 30           // (FS-1)/2
#define DENOM 7442.0f    // FS*FS*C
#define EPS_ 1e-7f

#define TOT_F   (N_*H_*W_*C_)        // 33554432 floats
#define ROWS    (N_*H_)              // 16384
#define NPIXCOL (N_*W_)              // 16384 pixel columns (float2 view)

// K1/K3 segmentation
#define SEG1 8
#define RPS1 (H_/SEG1)               // 128 rows per segment
#define SEG3 8
#define RPS3 (H_/SEG3)               // 128

// K2 config
#define K2_THREADS 512
#define K2_ITEMS   2                 // pixel columns per thread (512*2 = 1024)

// Scratch (static __device__ — no allocations allowed)
__device__ float  g_Vx[TOT_F];            // 128 MB: vertical box sums of x
__device__ float  g_out[TOT_F];           // 128 MB: out = x - avg(x)
__device__ float4 g_HB[N_*H_*W_];         // 256 MB: horiz window sums of (out, out^2)

static __device__ __forceinline__ float2 f2add(float2 a, float2 b){ return make_float2(a.x+b.x, a.y+b.y); }
static __device__ __forceinline__ float2 f2sub(float2 a, float2 b){ return make_float2(a.x-b.x, a.y-b.y); }
static __device__ __forceinline__ float4 f4add(float4 a, float4 b){ return make_float4(a.x+b.x, a.y+b.y, a.z+b.z, a.w+b.w); }
static __device__ __forceinline__ float4 f4sub(float4 a, float4 b){ return make_float4(a.x-b.x, a.y-b.y, a.z-b.z, a.w-b.w); }

// ---------------------------------------------------------------------------
// K1: vertical sliding-window sum of x -> g_Vx. float2 columns (one pixel
// column, both channels). 512 blocks x 256 thr; SEG1=8 row segments.
// ---------------------------------------------------------------------------
__global__ __launch_bounds__(256) void k1_vbox(const float* __restrict__ x)
{
    int gid = blockIdx.x * blockDim.x + threadIdx.x;   // 131072 total
    int col = gid & (NPIXCOL - 1);                     // 0..16383  (n, w)
    int seg = gid >> 14;                               // 0..7
    int n   = col >> 10;
    int w   = col & (W_ - 1);

    size_t base = (size_t)n * (H_*W_) + w;             // float2 units, row stride W_
    const float2* xp = reinterpret_cast<const float2*>(x) + base;
    float2*       vp = reinterpret_cast<float2*>(g_Vx) + base;

    int r0 = seg * RPS1;
    float2 sum = make_float2(0.f, 0.f);
    // warm-up: unrolled so loads batch (MLP), predicated off below row 0
    #pragma unroll
    for (int jj = 0; jj < 2 * RAD; ++jj) {
        int j = r0 - RAD + jj;
        if (j >= 0) sum = f2add(sum, xp[(size_t)j * W_]);
    }

    #pragma unroll 4
    for (int h = r0; h < r0 + RPS1; ++h) {
        int hn = h + RAD;
        if (hn < H_) sum = f2add(sum, xp[(size_t)hn * W_]);
        vp[(size_t)h * W_] = sum;
        int ho = h - RAD;
        if (ho >= 0) sum = f2sub(sum, xp[(size_t)ho * W_]);
    }
}

// ---------------------------------------------------------------------------
// K2: one block per row (n*H+h). 512 threads x 2 pixel columns.
//  1) prefix-scan Vx row (float2) -> horizontal window -> a
//  2) out = x - a  (store to g_out)
//  3) prefix-scan (out, out^2) as float4 -> horizontal window sums -> g_HB
// ---------------------------------------------------------------------------
__global__ __launch_bounds__(K2_THREADS) void k2_row(const float* __restrict__ x)
{
    const int row  = blockIdx.x;                 // n*H + h
    const int t    = threadIdx.x;
    const int lane = t & 31;
    const int wid  = t >> 5;                     // 0..15
    const unsigned FULL = 0xffffffffu;

    const float2* xg = reinterpret_cast<const float2*>(x)     + (size_t)row * W_;
    const float2* vg = reinterpret_cast<const float2*>(g_Vx)  + (size_t)row * W_;
    float2*       og = reinterpret_cast<float2*>(g_out)       + (size_t)row * W_;
    float4*       hb = g_HB                                   + (size_t)row * W_;

    __shared__ float2 sP[W_];        // prefix of Vx row
    __shared__ float4 sQ[W_];        // prefix of (out, out^2)
    __shared__ float2 wsum2[16];
    __shared__ float4 wsum4[16];

    const int base = t * K2_ITEMS;

    // ---- load Vx + x chunks ----
    float2 v[K2_ITEMS], xr[K2_ITEMS];
    #pragma unroll
    for (int i = 0; i < K2_ITEMS; ++i) { v[i] = vg[base + i]; xr[i] = xg[base + i]; }

    // ---- scan #1: float2 inclusive prefix of Vx row ----
    #pragma unroll
    for (int i = 1; i < K2_ITEMS; ++i) v[i] = f2add(v[i], v[i-1]);
    float2 tot2 = v[K2_ITEMS-1];
    float2 ws2 = tot2;
    #pragma unroll
    for (int d = 1; d < 32; d <<= 1) {
        float ux = __shfl_up_sync(FULL, ws2.x, d);
        float uy = __shfl_up_sync(FULL, ws2.y, d);
        if (lane >= d) { ws2.x += ux; ws2.y += uy; }
    }
    if (lane == 31) wsum2[wid] = ws2;
    __syncthreads();
    float2 off2 = f2sub(ws2, tot2);              // exclusive within warp
    #pragma unroll
    for (int k = 0; k < 16; ++k)
        if (k < wid) off2 = f2add(off2, wsum2[k]);
    #pragma unroll
    for (int i = 0; i < K2_ITEMS; ++i) sP[base + i] = f2add(off2, v[i]);
    __syncthreads();

    // ---- a = horiz window of sP / DENOM ; out = x - a ----
    const float inv = 1.0f / DENOM;
    float4 q[K2_ITEMS];
    #pragma unroll
    for (int i = 0; i < K2_ITEMS; ++i) {
        int w  = base + i;
        int hi = min(w + RAD, W_ - 1);
        float2 s = sP[hi];
        if (w >= RAD + 1) s = f2sub(s, sP[w - RAD - 1]);
        float2 o = make_float2(xr[i].x - s.x * inv, xr[i].y - s.y * inv);
        og[w] = o;
        q[i] = make_float4(o.x, o.y, o.x * o.x, o.y * o.y);
    }

    // ---- scan #2: float4 inclusive prefix of (out, out^2) ----
    #pragma unroll
    for (int i = 1; i < K2_ITEMS; ++i) q[i] = f4add(q[i], q[i-1]);
    float4 tot4 = q[K2_ITEMS-1];
    float4 ws4 = tot4;
    #pragma unroll
    for (int d = 1; d < 32; d <<= 1) {
        float ux = __shfl_up_sync(FULL, ws4.x, d);
        float uy = __shfl_up_sync(FULL, ws4.y, d);
        float uz = __shfl_up_sync(FULL, ws4.z, d);
        float uw = __shfl_up_sync(FULL, ws4.w, d);
        if (lane >= d) { ws4.x += ux; ws4.y += uy; ws4.z += uz; ws4.w += uw; }
    }
    if (lane == 31) wsum4[wid] = ws4;
    __syncthreads();
    float4 off4 = f4sub(ws4, tot4);
    #pragma unroll
    for (int k = 0; k < 16; ++k)
        if (k < wid) off4 = f4add(off4, wsum4[k]);
    #pragma unroll
    for (int i = 0; i < K2_ITEMS; ++i) sQ[base + i] = f4add(off4, q[i]);
    __syncthreads();

    // ---- horizontal window sums of (out, out^2) -> g_HB ----
    #pragma unroll
    for (int i = 0; i < K2_ITEMS; ++i) {
        int w  = base + i;
        int hi = min(w + RAD, W_ - 1);
        float4 s = sQ[hi];
        if (w >= RAD + 1) s = f4sub(s, sQ[w - RAD - 1]);
        hb[w] = s;
    }
}

// ---------------------------------------------------------------------------
// K3: vertical sliding float4 sum of g_HB -> (b, c); finalize:
//     res = out / (sqrt(c - b^2) + eps)
// 512 blocks; SEG3=8 row segments per column.
// ---------------------------------------------------------------------------
__global__ __launch_bounds__(256) void k3_vfin(float* __restrict__ outp)
{
    int gid = blockIdx.x * blockDim.x + threadIdx.x;   // 131072 total
    int col = gid & (NPIXCOL - 1);                     // 0..16383  (n, w)
    int seg = gid >> 14;                               // 0..7
    int n   = col >> 10;
    int w   = col & (W_ - 1);

    size_t cbase = (size_t)n * (H_*W_) + w;
    const float4* hb = g_HB + cbase;
    const float2* og = reinterpret_cast<const float2*>(g_out) + cbase;
    float2*       rp = reinterpret_cast<float2*>(outp) + cbase;

    int r0 = seg * RPS3;
    float4 s = make_float4(0.f, 0.f, 0.f, 0.f);
    // warm-up: unrolled so loads batch (MLP), predicated off below row 0
    #pragma unroll
    for (int jj = 0; jj < 2 * RAD; ++jj) {
        int j = r0 - RAD + jj;
        if (j >= 0) s = f4add(s, hb[(size_t)j * W_]);
    }

    const float inv = 1.0f / DENOM;
    #pragma unroll 4
    for (int h = r0; h < r0 + RPS3; ++h) {
        int hn = h + RAD;
        if (hn < H_) s = f4add(s, hb[(size_t)hn * W_]);

        float b0 = s.x * inv, b1 = s.y * inv;
        float c0 = s.z * inv, c1 = s.w * inv;
        float sd0 = sqrtf(fmaxf(c0 - b0 * b0, 0.f)) + EPS_;
        float sd1 = sqrtf(fmaxf(c1 - b1 * b1, 0.f)) + EPS_;

        float2 o = og[(size_t)h * W_];
        float2 r;
        r.x = o.x / sd0;
        r.y = o.y / sd1;
        rp[(size_t)h * W_] = r;

        int ho = h - RAD;
        if (ho >= 0) s = f4sub(s, hb[(size_t)ho * W_]);
    }
}

extern "C" void kernel_launch(void* const* d_in, const int* in_sizes, int n_in,
                              void* d_out, int out_size)
{
    const float* x = (const float*)d_in[0];
    (void)in_sizes; (void)n_in; (void)out_size;

    k1_vbox<<<(NPIXCOL * SEG1) / 256, 256>>>(x);            // 512 blocks
    k2_row <<<ROWS, K2_THREADS>>>(x);                       // 16384 blocks
    k3_vfin<<<(NPIXCOL * SEG3) / 256, 256>>>((float*)d_out);// 512 blocks
}